// round 15
// baseline (speedup 1.0000x reference)
#include <cuda_runtime.h>
#include <cuda_fp16.h>
#include <math.h>
#include <stdint.h>

// ---------------------------------------------------------------------------
// TransformerBlock B=2,S=2048,D=1024,H=16,Dk=64,DFF=4096
// GEMMs: mma.sync f16, CTA 128x256, 16 warps x (32x64), 3-stage cp.async,
// 1 CTA/SM (16 warps/SM). QKV token-major, exp2-domain softmax,
// single-pass LayerNorm.
// ---------------------------------------------------------------------------

#define D_MODEL 1024
#define NTOK    4096
#define NHEAD   16
#define DK      64
#define DFF     4096
#define SEQ     2048
#define EPS     1e-5f
#define QS      3072              // qkv token-major row stride (elements)
#define QSCALE  0.180336880111120f  // 0.125 * log2(e)

// ------------------------- scratch (static device mem) ---------------------
__device__ half  g_qkv[NTOK * 3 * D_MODEL];       // [token, q|k|v] token-major
__device__ half  g_ctx[NTOK * D_MODEL];
__device__ half  g_xh[NTOK * D_MODEL];
__device__ half  g_ath[NTOK * D_MODEL];
__device__ half  g_hh[NTOK * DFF];
__device__ float g_y[NTOK * D_MODEL];
__device__ float g_attn[NTOK * D_MODEL];

__device__ half  g_wqkv[3 * D_MODEL * D_MODEL];   // wq | wk | wv rows
__device__ half  g_wo[D_MODEL * D_MODEL];
__device__ half  g_w1[DFF * D_MODEL];
__device__ half  g_w2[D_MODEL * DFF];
__device__ float g_bqkv[3 * D_MODEL];

// ------------------------------ helpers ------------------------------------
__device__ __forceinline__ uint32_t smem_u32(const void* p) {
    uint32_t a;
    asm("{ .reg .u64 t; cvta.to.shared.u64 t, %1; cvt.u32.u64 %0, t; }" : "=r"(a) : "l"(p));
    return a;
}
#define CP_ASYNC16(dst, src) \
    asm volatile("cp.async.cg.shared.global [%0], [%1], 16;" :: "r"(dst), "l"(src))
#define CP_COMMIT() asm volatile("cp.async.commit_group;")
#define CP_WAIT0()  asm volatile("cp.async.wait_group 0;" ::: "memory")
#define CP_WAIT1()  asm volatile("cp.async.wait_group 1;" ::: "memory")

#define LDMATRIX_X4(r0, r1, r2, r3, a) \
    asm volatile("ldmatrix.sync.aligned.m8n8.x4.shared.b16 {%0,%1,%2,%3}, [%4];" \
                 : "=r"(r0), "=r"(r1), "=r"(r2), "=r"(r3) : "r"(a))
#define LDMATRIX_X4_TRANS(r0, r1, r2, r3, a) \
    asm volatile("ldmatrix.sync.aligned.m8n8.x4.trans.shared.b16 {%0,%1,%2,%3}, [%4];" \
                 : "=r"(r0), "=r"(r1), "=r"(r2), "=r"(r3) : "r"(a))

#define MMA16816(c, a, b) \
    asm volatile("mma.sync.aligned.m16n8k16.row.col.f32.f16.f16.f32 " \
                 "{%0,%1,%2,%3}, {%4,%5,%6,%7}, {%8,%9}, {%0,%1,%2,%3};" \
                 : "+f"((c)[0]), "+f"((c)[1]), "+f"((c)[2]), "+f"((c)[3]) \
                 : "r"((a)[0]), "r"((a)[1]), "r"((a)[2]), "r"((a)[3]), \
                   "r"((b)[0]), "r"((b)[1]))

__device__ __forceinline__ float gelu_f(float x) {
    return 0.5f * x * (1.0f + erff(x * 0.70710678118654752f));
}
__device__ __forceinline__ uint32_t h2pack(float a, float b) {
    half2 h = __floats2half2_rn(a, b);
    return *(uint32_t*)&h;
}

// ------------------------------ MMA GEMM -----------------------------------
// C[M,N] = A_f16[M,K] @ W_f16[N,K]^T (fp32 accum).
// CTA 128x256, 16 warps = 4 along M x 4 along N, warp tile 32x64. BK=64.
#define MODE_QKV  1
#define MODE_RES  2
#define MODE_GELU 3

#define ROWB    144              // 64 f16 = 128B data + 16B pad (conflict-free)
#define ATILEB  (128 * ROWB)     // 18432
#define BTILEB  (256 * ROWB)     // 36864
#define STAGEB  (ATILEB + BTILEB)// 55296
#define GEMM_SMEM (3 * STAGEB)   // 165888

template <int MODE>
__global__ void __launch_bounds__(512, 1) gemm_mma(
    const half* __restrict__ A, const half* __restrict__ W,
    const float* __restrict__ bias, const float* __restrict__ res,
    float* __restrict__ Cf, half* __restrict__ Ch,
    int M, int N, int K)
{
    extern __shared__ __align__(128) char dsm[];
    const uint32_t sbase = smem_u32(dsm);

    const int tid    = threadIdx.x;
    const int lane   = tid & 31;
    const int warp   = tid >> 5;
    const int warp_m = warp & 3;        // 4 along M -> 32 rows each
    const int warp_n = warp >> 2;       // 4 along N -> 64 cols each
    const int brow   = blockIdx.y * 128;
    const int bcol   = blockIdx.x * 256;

    const half* Ap = A + (size_t)brow * K;
    const half* Wp = W + (size_t)bcol * K;

    // ldmatrix lane addresses
    const int g = lane >> 3, r = lane & 7;
    const uint32_t aoff = (uint32_t)((warp_m * 32 + (g & 1) * 8 + r) * ROWB + (g >> 1) * 16);
    const uint32_t boff = (uint32_t)((warp_n * 64 + (g >> 1) * 8 + r) * ROWB + (g & 1) * 16);

    float acc[2][8][4];
    #pragma unroll
    for (int i = 0; i < 2; i++)
        #pragma unroll
        for (int j = 0; j < 8; j++)
            #pragma unroll
            for (int c = 0; c < 4; c++) acc[i][j][c] = 0.0f;

    const int T = K >> 6;   // BK = 64

    // prologue: issue stages 0 and 1 as two commit groups
    #pragma unroll
    for (int s = 0; s < 2; s++) {
        const uint32_t st = sbase + (uint32_t)s * STAGEB;
        const int k0 = s * 64;
        #pragma unroll
        for (int i = 0; i < 2; i++) {       // A: 1024 chunks / 512 thr
            const int idx = tid + i * 512;
            const int row = idx >> 3, c = idx & 7;
            CP_ASYNC16(st + (uint32_t)(row * ROWB + c * 16), Ap + (size_t)row * K + k0 + c * 8);
        }
        #pragma unroll
        for (int i = 0; i < 4; i++) {       // B: 2048 chunks / 512 thr
            const int idx = tid + i * 512;
            const int row = idx >> 3, c = idx & 7;
            CP_ASYNC16(st + ATILEB + (uint32_t)(row * ROWB + c * 16), Wp + (size_t)row * K + k0 + c * 8);
        }
        CP_COMMIT();
    }

    int stage = 0;
    for (int t = 0; t < T; t++) {
        if (t == T - 1) CP_WAIT0(); else CP_WAIT1();
        __syncthreads();

        const uint32_t cur = sbase + (uint32_t)stage * STAGEB;

        if (t + 2 < T) {
            const int k0 = (t + 2) * 64;
            int ns = stage + 2; if (ns >= 3) ns -= 3;
            const uint32_t nxt = sbase + (uint32_t)ns * STAGEB;
            #pragma unroll
            for (int i = 0; i < 2; i++) {
                const int idx = tid + i * 512;
                const int row = idx >> 3, c = idx & 7;
                CP_ASYNC16(nxt + (uint32_t)(row * ROWB + c * 16), Ap + (size_t)row * K + k0 + c * 8);
            }
            #pragma unroll
            for (int i = 0; i < 4; i++) {
                const int idx = tid + i * 512;
                const int row = idx >> 3, c = idx & 7;
                CP_ASYNC16(nxt + ATILEB + (uint32_t)(row * ROWB + c * 16), Wp + (size_t)row * K + k0 + c * 8);
            }
            CP_COMMIT();
        }

        const uint32_t sA = cur + aoff;
        const uint32_t sB = cur + ATILEB + boff;

        #pragma unroll
        for (int ks = 0; ks < 4; ks++) {
            const uint32_t ko = ks * 32;   // 16 f16 = 32B
            uint32_t a[2][4], bb[8][2];

            #pragma unroll
            for (int mi = 0; mi < 2; mi++)
                LDMATRIX_X4(a[mi][0], a[mi][1], a[mi][2], a[mi][3],
                            sA + mi * (16 * ROWB) + ko);
            #pragma unroll
            for (int np = 0; np < 4; np++)
                LDMATRIX_X4(bb[np * 2][0], bb[np * 2][1], bb[np * 2 + 1][0], bb[np * 2 + 1][1],
                            sB + np * (16 * ROWB) + ko);
            #pragma unroll
            for (int mi = 0; mi < 2; mi++)
                #pragma unroll
                for (int ni = 0; ni < 8; ni++)
                    MMA16816(acc[mi][ni], a[mi], bb[ni]);
        }

        if (++stage == 3) stage = 0;
    }

    // ------------------------------ epilogue -------------------------------
    const int mbase = brow + warp_m * 32 + (lane >> 2);
    const int nbase = bcol + warp_n * 64 + (lane & 3) * 2;

    #pragma unroll
    for (int mi = 0; mi < 2; mi++) {
        #pragma unroll
        for (int half_ = 0; half_ < 2; half_++) {
            const int m = mbase + mi * 16 + half_ * 8;
            #pragma unroll
            for (int ni = 0; ni < 8; ni++) {
                const int n = nbase + ni * 8;
                float vx = acc[mi][ni][half_ * 2 + 0];
                float vy = acc[mi][ni][half_ * 2 + 1];
                const float2 bb2 = *(const float2*)(bias + n);
                vx += bb2.x; vy += bb2.y;
                if (MODE == MODE_RES) {
                    const float2 rr = *(const float2*)(res + (size_t)m * N + n);
                    float2 o; o.x = vx + rr.x; o.y = vy + rr.y;
                    *(float2*)(Cf + (size_t)m * N + n) = o;
                } else if (MODE == MODE_QKV) {
                    // token-major [NTOK, 3072]; Q cols scaled into exp2 domain
                    const float sc = (n < D_MODEL) ? QSCALE : 1.0f;
                    half2 o = __floats2half2_rn(vx * sc, vy * sc);
                    *(half2*)(Ch + (size_t)m * QS + n) = o;
                } else {  // GELU
                    half2 o = __floats2half2_rn(gelu_f(vx), gelu_f(vy));
                    *(half2*)(Ch + (size_t)m * N + n) = o;
                }
            }
        }
    }
}

// ---------------- fused conversion kernel (all weights + x + bias) ---------
#define U_X   524288u
#define U_W   131072u
#define B0    (U_X)
#define B1    (B0 + U_W)
#define B2    (B1 + U_W)
#define B3    (B2 + U_W)
#define B4    (B3 + U_W)
#define B5    (B4 + U_X)
#define B6    (B5 + U_X)

__global__ void __launch_bounds__(256) cvt_all(
    const float* __restrict__ x,
    const float* __restrict__ wq, const float* __restrict__ wk,
    const float* __restrict__ wv, const float* __restrict__ wo,
    const float* __restrict__ w1, const float* __restrict__ w2,
    const float* __restrict__ bq, const float* __restrict__ bk,
    const float* __restrict__ bv,
    half* __restrict__ xh, half* __restrict__ wqkvh, half* __restrict__ woh,
    half* __restrict__ w1h, half* __restrict__ w2h, float* __restrict__ bqkv)
{
    const uint32_t gtid = blockIdx.x * blockDim.x + threadIdx.x;
    const uint32_t gstride = gridDim.x * blockDim.x;

    if (gtid < 768) {
        float4 v = (gtid < 256) ? ((const float4*)bq)[gtid]
                 : (gtid < 512) ? ((const float4*)bk)[gtid - 256]
                                : ((const float4*)bv)[gtid - 512];
        ((float4*)bqkv)[gtid] = v;
    }

    for (uint32_t u = gtid; u < B6; u += gstride) {
        const float* src; half* dst; uint32_t off;
        if (u < B0)      { src = x;  dst = xh;                off = u; }
        else if (u < B1) { src = wq; dst = wqkvh;             off = u - B0; }
        else if (u < B2) { src = wk; dst = wqkvh + 1048576;   off = u - B1; }
        else if (u < B3) { src = wv; dst = wqkvh + 2097152;   off = u - B2; }
        else if (u < B4) { src = wo; dst = woh;               off = u - B3; }
        else if (u < B5) { src = w1; dst = w1h;               off = u - B4; }
        else             { src = w2; dst = w2h;               off = u - B5; }

        const float4 v0 = ((const float4*)src)[off * 2 + 0];
        const float4 v1 = ((const float4*)src)[off * 2 + 1];
        uint4 o;
        o.x = h2pack(v0.x, v0.y);
        o.y = h2pack(v0.z, v0.w);
        o.z = h2pack(v1.x, v1.y);
        o.w = h2pack(v1.z, v1.w);
        ((uint4*)dst)[off] = o;
    }
}

// ---------------------- tensor-core flash attention ------------------------
// Q pre-scaled into exp2 domain. qkv token-major [NTOK,3072].
// ctx: [B, S, 1024] f16. 3-stage K/V pipeline, 64-key blocks, 8 warps.
#define KROWB 144
#define ATT_SQ_B  (128 * KROWB)              // 18432
#define ATT_KV_B  (64 * KROWB)               // 9216
#define ATT_SMEM  (ATT_SQ_B + 6 * ATT_KV_B)  // 73728
#define NKB       (SEQ / 64)                 // 32

__global__ void __launch_bounds__(256, 2) attn_tc(
    const half* __restrict__ qkv, half* __restrict__ ctx)
{
    extern __shared__ __align__(128) char sm[];
    const uint32_t sb = smem_u32(sm);
    const uint32_t sQ = sb;

    const int tid  = threadIdx.x;
    const int lane = tid & 31;
    const int warp = tid >> 5;
    const int bh   = blockIdx.y;
    const int q0   = blockIdx.x * 128;
    const int b    = bh >> 4, h = bh & 15;

    const half* Qp = qkv + ((size_t)(b * SEQ + q0)) * QS + h * DK;
    const half* Kp = qkv + ((size_t)(b * SEQ)) * QS + h * DK + D_MODEL;
    const half* Vp = qkv + ((size_t)(b * SEQ)) * QS + h * DK + 2 * D_MODEL;

    #pragma unroll
    for (int i = 0; i < 4; i++) {
        const int idx = tid + i * 256;
        const int row = idx >> 3, c = idx & 7;
        CP_ASYNC16(sQ + (uint32_t)(row * KROWB + c * 16), Qp + (size_t)row * QS + c * 8);
    }
    {
        const uint32_t sk = sb + ATT_SQ_B, sv = sk + ATT_KV_B;
        #pragma unroll
        for (int i = 0; i < 2; i++) {
            const int idx = tid + i * 256;
            const int row = idx >> 3, c = idx & 7;
            CP_ASYNC16(sk + (uint32_t)(row * KROWB + c * 16), Kp + (size_t)row * QS + c * 8);
            CP_ASYNC16(sv + (uint32_t)(row * KROWB + c * 16), Vp + (size_t)row * QS + c * 8);
        }
    }
    CP_COMMIT();
    {
        const uint32_t sk = sb + ATT_SQ_B + 2 * ATT_KV_B, sv = sk + ATT_KV_B;
        #pragma unroll
        for (int i = 0; i < 2; i++) {
            const int idx = tid + i * 256;
            const int row = idx >> 3, c = idx & 7;
            CP_ASYNC16(sk + (uint32_t)(row * KROWB + c * 16), Kp + (size_t)(64 + row) * QS + c * 8);
            CP_ASYNC16(sv + (uint32_t)(row * KROWB + c * 16), Vp + (size_t)(64 + row) * QS + c * 8);
        }
    }
    CP_COMMIT();

    const int g = lane >> 3, r8 = lane & 7;

    CP_WAIT1();
    __syncthreads();

    uint32_t qa[4][4];
    {
        const uint32_t ao = sQ + (uint32_t)((warp * 16 + (g & 1) * 8 + r8) * KROWB + (g >> 1) * 16);
        #pragma unroll
        for (int kf = 0; kf < 4; kf++)
            LDMATRIX_X4(qa[kf][0], qa[kf][1], qa[kf][2], qa[kf][3], ao + kf * 32);
    }

    float oacc[8][4];
    #pragma unroll
    for (int i = 0; i < 8; i++)
        #pragma unroll
        for (int c = 0; c < 4; c++) oacc[i][c] = 0.0f;
    float mrun0 = -1e30f, mrun1 = -1e30f, lrun0 = 0.0f, lrun1 = 0.0f;

    const uint32_t koff = (uint32_t)(((g >> 1) * 8 + r8) * KROWB + (g & 1) * 16);
    const uint32_t voff = (uint32_t)(((g & 1) * 8 + r8) * KROWB + (g >> 1) * 16);

    int stage = 0;
    for (int kb = 0; kb < NKB; kb++) {
        if (kb == NKB - 1) CP_WAIT0(); else CP_WAIT1();
        __syncthreads();

        const uint32_t sk = sb + ATT_SQ_B + (uint32_t)stage * (2 * ATT_KV_B);
        const uint32_t sv = sk + ATT_KV_B;

        if (kb + 2 < NKB) {
            int ns = stage + 2; if (ns >= 3) ns -= 3;
            const uint32_t nk = sb + ATT_SQ_B + (uint32_t)ns * (2 * ATT_KV_B);
            const uint32_t nv = nk + ATT_KV_B;
            const int rbase = (kb + 2) * 64;
            #pragma unroll
            for (int i = 0; i < 2; i++) {
                const int idx = tid + i * 256;
                const int row = idx >> 3, c = idx & 7;
                CP_ASYNC16(nk + (uint32_t)(row * KROWB + c * 16), Kp + (size_t)(rbase + row) * QS + c * 8);
                CP_ASYNC16(nv + (uint32_t)(row * KROWB + c * 16), Vp + (size_t)(rbase + row) * QS + c * 8);
            }
            CP_COMMIT();
        }

        // ---- S' = (Q*log2e/8) @ K^T  (exp2 domain) ----
        float sf[8][4];
        #pragma unroll
        for (int i = 0; i < 8; i++)
            #pragma unroll
            for (int c = 0; c < 4; c++) sf[i][c] = 0.0f;

        #pragma unroll
        for (int kf = 0; kf < 4; kf++) {
            uint32_t kbv[8][2];
            const uint32_t bo = sk + koff + kf * 32;
            #pragma unroll
            for (int np = 0; np < 4; np++)
                LDMATRIX_X4(kbv[np * 2][0], kbv[np * 2][1], kbv[np * 2 + 1][0], kbv[np * 2 + 1][1],
                            bo + np * (16 * KROWB));
            #pragma unroll
            for (int ni = 0; ni < 8; ni++)
                MMA16816(sf[ni], qa[kf], kbv[ni]);
        }

        // ---- online softmax (exp2 domain) ----
        float mx0 = -1e30f, mx1 = -1e30f;
        #pragma unroll
        for (int ni = 0; ni < 8; ni++) {
            mx0 = fmaxf(mx0, fmaxf(sf[ni][0], sf[ni][1]));
            mx1 = fmaxf(mx1, fmaxf(sf[ni][2], sf[ni][3]));
        }
        mx0 = fmaxf(mx0, __shfl_xor_sync(0xffffffffu, mx0, 1));
        mx0 = fmaxf(mx0, __shfl_xor_sync(0xffffffffu, mx0, 2));
        mx1 = fmaxf(mx1, __shfl_xor_sync(0xffffffffu, mx1, 1));
        mx1 = fmaxf(mx1, __shfl_xor_sync(0xffffffffu, mx1, 2));

        const float mn0 = fmaxf(mrun0, mx0), mn1 = fmaxf(mrun1, mx1);
        const float cr0 = exp2f(mrun0 - mn0), cr1 = exp2f(mrun1 - mn1);
        float s0 = 0.0f, s1 = 0.0f;
        #pragma unroll
        for (int ni = 0; ni < 8; ni++) {
            sf[ni][0] = exp2f(sf[ni][0] - mn0); s0 += sf[ni][0];
            sf[ni][1] = exp2f(sf[ni][1] - mn0); s0 += sf[ni][1];
            sf[ni][2] = exp2f(sf[ni][2] - mn1); s1 += sf[ni][2];
            sf[ni][3] = exp2f(sf[ni][3] - mn1); s1 += sf[ni][3];
        }
        s0 += __shfl_xor_sync(0xffffffffu, s0, 1);
        s0 += __shfl_xor_sync(0xffffffffu, s0, 2);
        s1 += __shfl_xor_sync(0xffffffffu, s1, 1);
        s1 += __shfl_xor_sync(0xffffffffu, s1, 2);
        lrun0 = lrun0 * cr0 + s0;
        lrun1 = lrun1 * cr1 + s1;
        #pragma unroll
        for (int ni = 0; ni < 8; ni++) {
            oacc[ni][0] *= cr0; oacc[ni][1] *= cr0;
            oacc[ni][2] *= cr1; oacc[ni][3] *= cr1;
        }
        mrun0 = mn0; mrun1 = mn1;

        // ---- O += P @ V ----
        #pragma unroll
        for (int kf = 0; kf < 4; kf++) {
            uint32_t pa[4];
            pa[0] = h2pack(sf[2 * kf][0],     sf[2 * kf][1]);
            pa[1] = h2pack(sf[2 * kf][2],     sf[2 * kf][3]);
            pa[2] = h2pack(sf[2 * kf + 1][0], sf[2 * kf + 1][1]);
            pa[3] = h2pack(sf[2 * kf + 1][2], sf[2 * kf + 1][3]);

            uint32_t vb[8][2];
            const uint32_t vo = sv + voff + kf * (16 * KROWB);
            #pragma unroll
            for (int np = 0; np < 4; np++)
                LDMATRIX_X4_TRANS(vb[np * 2][0], vb[np * 2][1], vb[np * 2 + 1][0], vb[np * 2 + 1][1],
                                  vo + np * 32);
            #pragma unroll
            for (int ni = 0; ni < 8; ni++)
                MMA16816(oacc[ni], pa, vb[ni]);
        }

        if (++stage == 3) stage = 0;
    }

    // ---- write ctx ----
    const float i0 = 1.0f / lrun0, i1 = 1.0f / lrun1;
    const int tok = q0 + warp * 16 + (lane >> 2);
    half* p0 = ctx + (size_t)(b * SEQ + tok) * D_MODEL + h * DK + (lane & 3) * 2;
    half* p1 = p0 + 8 * D_MODEL;
    #pragma unroll
    for (int ni = 0; ni < 8; ni++) {
        *(half2*)(p0 + ni * 8) = __floats2half2_rn(oacc[ni][0] * i0, oacc[ni][1] * i0);
        *(half2*)(p1 + ni * 8) = __floats2half2_rn(oacc[ni][2] * i1, oacc[ni][3] * i1);
    }
}

// ------------------- LayerNorm (single-pass stats) --------------------------
template <bool HOUT>
__global__ void __launch_bounds__(256) ln_kernel(
    const float* __restrict__ X, const float* __restrict__ G,
    const float* __restrict__ Bb, float* __restrict__ Y, half* __restrict__ Yh)
{
    __shared__ float redS[8];
    __shared__ float redQ[8];
    __shared__ float stat[2];
    const int row = blockIdx.x;
    const int tid = threadIdx.x;
    const int lane = tid & 31, warp = tid >> 5;

    float4 v = *(const float4*)(X + (size_t)row * D_MODEL + tid * 4);

    float s = v.x + v.y + v.z + v.w;
    float q = v.x * v.x + v.y * v.y + v.z * v.z + v.w * v.w;
    #pragma unroll
    for (int o = 16; o; o >>= 1) {
        s += __shfl_xor_sync(0xffffffffu, s, o);
        q += __shfl_xor_sync(0xffffffffu, q, o);
    }
    if (lane == 0) { redS[warp] = s; redQ[warp] = q; }
    __syncthreads();
    if (tid == 0) {
        float ts = 0.0f, tq = 0.0f;
        #pragma unroll
        for (int i = 0; i < 8; i++) { ts += redS[i]; tq += redQ[i]; }
        const float mu = ts * (1.0f / D_MODEL);
        stat[0] = mu;
        stat[1] = rsqrtf(tq * (1.0f / D_MODEL) - mu * mu + EPS);
    }
    __syncthreads();
    const float mu = stat[0];
    const float rstd = stat[1];

    const int c = tid * 4;
    float4 gg = *(const float4*)(G + c);
    float4 bb = *(const float4*)(Bb + c);
    float4 o;
    o.x = (v.x - mu) * rstd * gg.x + bb.x;
    o.y = (v.y - mu) * rstd * gg.y + bb.y;
    o.z = (v.z - mu) * rstd * gg.z + bb.z;
    o.w = (v.w - mu) * rstd * gg.w + bb.w;
    *(float4*)(Y + (size_t)row * D_MODEL + c) = o;

    if (HOUT) {
        *(half2*)(Yh + (size_t)row * D_MODEL + c)     = __floats2half2_rn(o.x, o.y);
        *(half2*)(Yh + (size_t)row * D_MODEL + c + 2) = __floats2half2_rn(o.z, o.w);
    }
}

// ------------------------------ launch -------------------------------------
extern "C" void kernel_launch(void* const* d_in, const int* in_sizes, int n_in,
                              void* d_out, int out_size)
{
    const float* x     = (const float*)d_in[0];
    const float* wq    = (const float*)d_in[1];
    const float* bq    = (const float*)d_in[2];
    const float* wk    = (const float*)d_in[3];
    const float* bk    = (const float*)d_in[4];
    const float* wv    = (const float*)d_in[5];
    const float* bv    = (const float*)d_in[6];
    const float* wo    = (const float*)d_in[7];
    const float* bo    = (const float*)d_in[8];
    const float* ln1_g = (const float*)d_in[9];
    const float* ln1_b = (const float*)d_in[10];
    const float* w1    = (const float*)d_in[11];
    const float* b1    = (const float*)d_in[12];
    const float* w2    = (const float*)d_in[13];
    const float* b2    = (const float*)d_in[14];
    const float* ln2_g = (const float*)d_in[15];
    const float* ln2_b = (const float*)d_in[16];
    float* out = (float*)d_out;

    half *qkv, *ctx, *xh, *ath, *hh, *wqkvh, *woh, *w1h, *w2h;
    float *y, *attn, *bqkv;
    cudaGetSymbolAddress((void**)&qkv,   g_qkv);
    cudaGetSymbolAddress((void**)&ctx,   g_ctx);
    cudaGetSymbolAddress((void**)&xh,    g_xh);
    cudaGetSymbolAddress((void**)&ath,   g_ath);
    cudaGetSymbolAddress((void**)&hh,    g_hh);
    cudaGetSymbolAddress((void**)&y,     g_y);
    cudaGetSymbolAddress((void**)&attn,  g_attn);
    cudaGetSymbolAddress((void**)&wqkvh, g_wqkv);
    cudaGetSymbolAddress((void**)&woh,   g_wo);
    cudaGetSymbolAddress((void**)&w1h,   g_w1);
    cudaGetSymbolAddress((void**)&w2h,   g_w2);
    cudaGetSymbolAddress((void**)&bqkv,  g_bqkv);

    cudaFuncSetAttribute(gemm_mma<MODE_QKV>,  cudaFuncAttributeMaxDynamicSharedMemorySize, GEMM_SMEM);
    cudaFuncSetAttribute(gemm_mma<MODE_RES>,  cudaFuncAttributeMaxDynamicSharedMemorySize, GEMM_SMEM);
    cudaFuncSetAttribute(gemm_mma<MODE_GELU>, cudaFuncAttributeMaxDynamicSharedMemorySize, GEMM_SMEM);
    cudaFuncSetAttribute(attn_tc,             cudaFuncAttributeMaxDynamicSharedMemorySize, ATT_SMEM);

    // 0) one-shot conversion of x + all weights + bias pack
    cvt_all<<<2048, 256>>>(x, wq, wk, wv, wo, w1, w2, bq, bk, bv,
                           xh, wqkvh, woh, w1h, w2h, bqkv);

    const dim3 gblk(512);
    const dim3 blk(256);
    const dim3 gQ(3 * D_MODEL / 256, NTOK / 128);   // (12, 32)
    const dim3 gD(D_MODEL / 256,     NTOK / 128);   // (4, 32)
    const dim3 gF(DFF / 256,         NTOK / 128);   // (16, 32)

    // 1) fused QKV projection -> f16 token-major [NTOK, 3072]; Q in exp2 domain
    gemm_mma<MODE_QKV><<<gQ, gblk, GEMM_SMEM>>>(xh, wqkvh, bqkv, nullptr, nullptr, qkv,
                                                NTOK, 3 * D_MODEL, D_MODEL);

    // 2) flash attention -> ctx f16
    attn_tc<<<dim3(SEQ / 128, 2 * NHEAD), blk, ATT_SMEM>>>(qkv, ctx);

    // 3) O projection + residual -> y fp32
    gemm_mma<MODE_RES><<<gD, gblk, GEMM_SMEM>>>(ctx, woh, bo, x, y, nullptr,
                                                NTOK, D_MODEL, D_MODEL);

    // 4) LN1 -> attn fp32 + ath f16
    ln_kernel<true><<<NTOK, blk>>>(y, ln1_g, ln1_b, attn, ath);

    // 5) FF1 + GELU -> h f16
    gemm_mma<MODE_GELU><<<gF, gblk, GEMM_SMEM>>>(ath, w1h, b1, nullptr, nullptr, hh,
                                                 NTOK, DFF, D_MODEL);

    // 6) FF2 + residual -> y fp32
    gemm_mma<MODE_RES><<<gD, gblk, GEMM_SMEM>>>(hh, w2h, b2, attn, y, nullptr,
                                                NTOK, D_MODEL, DFF);

    // 7) LN2 -> out
    ln_kernel<false><<<NTOK, blk>>>(y, ln2_g, ln2_b, out, nullptr);
}

// round 16
// speedup vs baseline: 1.0658x; 1.0658x over previous
#include <cuda_runtime.h>
#include <cuda_fp16.h>
#include <math.h>
#include <stdint.h>

// ---------------------------------------------------------------------------
// TransformerBlock B=2,S=2048,D=1024,H=16,Dk=64,DFF=4096
// GEMMs: mma.sync f16 single-term, 8 warps x (32x64) per 128x128 CTA,
// 3-stage cp.async. QKV token-major [4096,3072], Q pre-scaled by
// 0.125*log2(e) (exp2-domain softmax). Single-pass LayerNorm stats.
// (R14 configuration — best measured: 529.6 us)
// ---------------------------------------------------------------------------

#define D_MODEL 1024
#define NTOK    4096
#define NHEAD   16
#define DK      64
#define DFF     4096
#define SEQ     2048
#define EPS     1e-5f
#define QS      3072              // qkv token-major row stride (elements)
#define QSCALE  0.180336880111120f  // 0.125 * log2(e)

// ------------------------- scratch (static device mem) ---------------------
__device__ half  g_qkv[NTOK * 3 * D_MODEL];       // [token, q|k|v] token-major
__device__ half  g_ctx[NTOK * D_MODEL];
__device__ half  g_xh[NTOK * D_MODEL];
__device__ half  g_ath[NTOK * D_MODEL];
__device__ half  g_hh[NTOK * DFF];
__device__ float g_y[NTOK * D_MODEL];
__device__ float g_attn[NTOK * D_MODEL];

__device__ half  g_wqkv[3 * D_MODEL * D_MODEL];   // wq | wk | wv rows
__device__ half  g_wo[D_MODEL * D_MODEL];
__device__ half  g_w1[DFF * D_MODEL];
__device__ half  g_w2[D_MODEL * DFF];
__device__ float g_bqkv[3 * D_MODEL];

// ------------------------------ helpers ------------------------------------
__device__ __forceinline__ uint32_t smem_u32(const void* p) {
    uint32_t a;
    asm("{ .reg .u64 t; cvta.to.shared.u64 t, %1; cvt.u32.u64 %0, t; }" : "=r"(a) : "l"(p));
    return a;
}
#define CP_ASYNC16(dst, src) \
    asm volatile("cp.async.cg.shared.global [%0], [%1], 16;" :: "r"(dst), "l"(src))
#define CP_COMMIT() asm volatile("cp.async.commit_group;")
#define CP_WAIT0()  asm volatile("cp.async.wait_group 0;" ::: "memory")
#define CP_WAIT1()  asm volatile("cp.async.wait_group 1;" ::: "memory")

#define LDMATRIX_X4(r0, r1, r2, r3, a) \
    asm volatile("ldmatrix.sync.aligned.m8n8.x4.shared.b16 {%0,%1,%2,%3}, [%4];" \
                 : "=r"(r0), "=r"(r1), "=r"(r2), "=r"(r3) : "r"(a))
#define LDMATRIX_X4_TRANS(r0, r1, r2, r3, a) \
    asm volatile("ldmatrix.sync.aligned.m8n8.x4.trans.shared.b16 {%0,%1,%2,%3}, [%4];" \
                 : "=r"(r0), "=r"(r1), "=r"(r2), "=r"(r3) : "r"(a))

#define MMA16816(c, a, b) \
    asm volatile("mma.sync.aligned.m16n8k16.row.col.f32.f16.f16.f32 " \
                 "{%0,%1,%2,%3}, {%4,%5,%6,%7}, {%8,%9}, {%0,%1,%2,%3};" \
                 : "+f"((c)[0]), "+f"((c)[1]), "+f"((c)[2]), "+f"((c)[3]) \
                 : "r"((a)[0]), "r"((a)[1]), "r"((a)[2]), "r"((a)[3]), \
                   "r"((b)[0]), "r"((b)[1]))

__device__ __forceinline__ float gelu_f(float x) {
    return 0.5f * x * (1.0f + erff(x * 0.70710678118654752f));
}
__device__ __forceinline__ uint32_t h2pack(float a, float b) {
    half2 h = __floats2half2_rn(a, b);
    return *(uint32_t*)&h;
}

// ------------------------------ MMA GEMM -----------------------------------
// C[M,N] = A_f16[M,K] @ W_f16[N,K]^T  (fp32 accum). BM=BN=128, BK=64, 3-stage.
#define MODE_QKV  1
#define MODE_RES  2
#define MODE_GELU 3

#define ROWB   144               // 64 f16 = 128B data + 16B pad (conflict-free)
#define TILEB  (128 * ROWB)      // 18432
#define STAGEB (2 * TILEB)       // 36864 (A + B)
#define GEMM_SMEM (3 * STAGEB)   // 110592

template <int MODE>
__global__ void __launch_bounds__(256, 2) gemm_mma(
    const half* __restrict__ A, const half* __restrict__ W,
    const float* __restrict__ bias, const float* __restrict__ res,
    float* __restrict__ Cf, half* __restrict__ Ch,
    int M, int N, int K)
{
    extern __shared__ __align__(128) char dsm[];
    const uint32_t sbase = smem_u32(dsm);

    const int tid    = threadIdx.x;
    const int lane   = tid & 31;
    const int warp   = tid >> 5;
    const int warp_m = warp & 3;        // 4 along M -> 32 rows each
    const int warp_n = warp >> 2;       // 2 along N -> 64 cols each
    const int brow   = blockIdx.y * 128;
    const int bcol   = blockIdx.x * 128;

    const half* Ap = A + (size_t)brow * K;
    const half* Wp = W + (size_t)bcol * K;

    // ldmatrix lane addresses
    const int g = lane >> 3, r = lane & 7;
    const uint32_t aoff = (uint32_t)((warp_m * 32 + (g & 1) * 8 + r) * ROWB + (g >> 1) * 16);
    const uint32_t boff = (uint32_t)((warp_n * 64 + (g >> 1) * 8 + r) * ROWB + (g & 1) * 16);

    float acc[2][8][4];
    #pragma unroll
    for (int i = 0; i < 2; i++)
        #pragma unroll
        for (int j = 0; j < 8; j++)
            #pragma unroll
            for (int c = 0; c < 4; c++) acc[i][j][c] = 0.0f;

    const int T = K >> 6;   // BK = 64

    // prologue: issue stages 0 and 1 as two commit groups
    #pragma unroll
    for (int s = 0; s < 2; s++) {
        const uint32_t st = sbase + (uint32_t)s * STAGEB;
        const int k0 = s * 64;
        #pragma unroll
        for (int i = 0; i < 4; i++) {
            const int idx = tid + i * 256;
            const int row = idx >> 3, c = idx & 7;
            const uint32_t so = (uint32_t)(row * ROWB + c * 16);
            CP_ASYNC16(st + so,         Ap + (size_t)row * K + k0 + c * 8);
            CP_ASYNC16(st + TILEB + so, Wp + (size_t)row * K + k0 + c * 8);
        }
        CP_COMMIT();
    }

    int stage = 0;
    for (int t = 0; t < T; t++) {
        if (t == T - 1) CP_WAIT0(); else CP_WAIT1();
        __syncthreads();

        const uint32_t cur = sbase + (uint32_t)stage * STAGEB;

        if (t + 2 < T) {
            const int k0 = (t + 2) * 64;
            int ns = stage + 2; if (ns >= 3) ns -= 3;
            const uint32_t nxt = sbase + (uint32_t)ns * STAGEB;
            #pragma unroll
            for (int i = 0; i < 4; i++) {
                const int idx = tid + i * 256;
                const int row = idx >> 3, c = idx & 7;
                const uint32_t so = (uint32_t)(row * ROWB + c * 16);
                CP_ASYNC16(nxt + so,         Ap + (size_t)row * K + k0 + c * 8);
                CP_ASYNC16(nxt + TILEB + so, Wp + (size_t)row * K + k0 + c * 8);
            }
            CP_COMMIT();
        }

        const uint32_t sA = cur + aoff;
        const uint32_t sB = cur + TILEB + boff;

        #pragma unroll
        for (int ks = 0; ks < 4; ks++) {
            const uint32_t ko = ks * 32;   // 16 f16 = 32B
            uint32_t a[2][4], bb[8][2];

            #pragma unroll
            for (int mi = 0; mi < 2; mi++)
                LDMATRIX_X4(a[mi][0], a[mi][1], a[mi][2], a[mi][3],
                            sA + mi * (16 * ROWB) + ko);
            #pragma unroll
            for (int np = 0; np < 4; np++)
                LDMATRIX_X4(bb[np * 2][0], bb[np * 2][1], bb[np * 2 + 1][0], bb[np * 2 + 1][1],
                            sB + np * (16 * ROWB) + ko);
            #pragma unroll
            for (int mi = 0; mi < 2; mi++)
                #pragma unroll
                for (int ni = 0; ni < 8; ni++)
                    MMA16816(acc[mi][ni], a[mi], bb[ni]);
        }

        if (++stage == 3) stage = 0;
    }

    // ------------------------------ epilogue -------------------------------
    const int mbase = brow + warp_m * 32 + (lane >> 2);
    const int nbase = bcol + warp_n * 64 + (lane & 3) * 2;

    #pragma unroll
    for (int mi = 0; mi < 2; mi++) {
        #pragma unroll
        for (int half_ = 0; half_ < 2; half_++) {
            const int m = mbase + mi * 16 + half_ * 8;
            #pragma unroll
            for (int ni = 0; ni < 8; ni++) {
                const int n = nbase + ni * 8;
                float vx = acc[mi][ni][half_ * 2 + 0];
                float vy = acc[mi][ni][half_ * 2 + 1];
                const float2 bb2 = *(const float2*)(bias + n);
                vx += bb2.x; vy += bb2.y;
                if (MODE == MODE_RES) {
                    const float2 rr = *(const float2*)(res + (size_t)m * N + n);
                    float2 o; o.x = vx + rr.x; o.y = vy + rr.y;
                    *(float2*)(Cf + (size_t)m * N + n) = o;
                } else if (MODE == MODE_QKV) {
                    // token-major [NTOK, 3072]; Q cols scaled into exp2 domain
                    const float sc = (n < D_MODEL) ? QSCALE : 1.0f;
                    half2 o = __floats2half2_rn(vx * sc, vy * sc);
                    *(half2*)(Ch + (size_t)m * QS + n) = o;
                } else {  // GELU
                    half2 o = __floats2half2_rn(gelu_f(vx), gelu_f(vy));
                    *(half2*)(Ch + (size_t)m * N + n) = o;
                }
            }
        }
    }
}

// ---------------- fused conversion kernel (all weights + x + bias) ---------
#define U_X   524288u
#define U_W   131072u
#define B0    (U_X)
#define B1    (B0 + U_W)
#define B2    (B1 + U_W)
#define B3    (B2 + U_W)
#define B4    (B3 + U_W)
#define B5    (B4 + U_X)
#define B6    (B5 + U_X)

__global__ void __launch_bounds__(256) cvt_all(
    const float* __restrict__ x,
    const float* __restrict__ wq, const float* __restrict__ wk,
    const float* __restrict__ wv, const float* __restrict__ wo,
    const float* __restrict__ w1, const float* __restrict__ w2,
    const float* __restrict__ bq, const float* __restrict__ bk,
    const float* __restrict__ bv,
    half* __restrict__ xh, half* __restrict__ wqkvh, half* __restrict__ woh,
    half* __restrict__ w1h, half* __restrict__ w2h, float* __restrict__ bqkv)
{
    const uint32_t gtid = blockIdx.x * blockDim.x + threadIdx.x;
    const uint32_t gstride = gridDim.x * blockDim.x;

    if (gtid < 768) {
        float4 v = (gtid < 256) ? ((const float4*)bq)[gtid]
                 : (gtid < 512) ? ((const float4*)bk)[gtid - 256]
                                : ((const float4*)bv)[gtid - 512];
        ((float4*)bqkv)[gtid] = v;
    }

    for (uint32_t u = gtid; u < B6; u += gstride) {
        const float* src; half* dst; uint32_t off;
        if (u < B0)      { src = x;  dst = xh;                off = u; }
        else if (u < B1) { src = wq; dst = wqkvh;             off = u - B0; }
        else if (u < B2) { src = wk; dst = wqkvh + 1048576;   off = u - B1; }
        else if (u < B3) { src = wv; dst = wqkvh + 2097152;   off = u - B2; }
        else if (u < B4) { src = wo; dst = woh;               off = u - B3; }
        else if (u < B5) { src = w1; dst = w1h;               off = u - B4; }
        else             { src = w2; dst = w2h;               off = u - B5; }

        const float4 v0 = ((const float4*)src)[off * 2 + 0];
        const float4 v1 = ((const float4*)src)[off * 2 + 1];
        uint4 o;
        o.x = h2pack(v0.x, v0.y);
        o.y = h2pack(v0.z, v0.w);
        o.z = h2pack(v1.x, v1.y);
        o.w = h2pack(v1.z, v1.w);
        ((uint4*)dst)[off] = o;
    }
}

// ---------------------- tensor-core flash attention ------------------------
// Q pre-scaled into exp2 domain. qkv token-major [NTOK,3072].
// ctx: [B, S, 1024] f16. 3-stage K/V pipeline, 64-key blocks, 8 warps.
#define KROWB 144
#define ATT_SQ_B  (128 * KROWB)              // 18432
#define ATT_KV_B  (64 * KROWB)               // 9216
#define ATT_SMEM  (ATT_SQ_B + 6 * ATT_KV_B)  // 73728
#define NKB       (SEQ / 64)                 // 32

__global__ void __launch_bounds__(256, 2) attn_tc(
    const half* __restrict__ qkv, half* __restrict__ ctx)
{
    extern __shared__ __align__(128) char sm[];
    const uint32_t sb = smem_u32(sm);
    const uint32_t sQ = sb;

    const int tid  = threadIdx.x;
    const int lane = tid & 31;
    const int warp = tid >> 5;
    const int bh   = blockIdx.y;
    const int q0   = blockIdx.x * 128;
    const int b    = bh >> 4, h = bh & 15;

    const half* Qp = qkv + ((size_t)(b * SEQ + q0)) * QS + h * DK;
    const half* Kp = qkv + ((size_t)(b * SEQ)) * QS + h * DK + D_MODEL;
    const half* Vp = qkv + ((size_t)(b * SEQ)) * QS + h * DK + 2 * D_MODEL;

    #pragma unroll
    for (int i = 0; i < 4; i++) {
        const int idx = tid + i * 256;
        const int row = idx >> 3, c = idx & 7;
        CP_ASYNC16(sQ + (uint32_t)(row * KROWB + c * 16), Qp + (size_t)row * QS + c * 8);
    }
    {
        const uint32_t sk = sb + ATT_SQ_B, sv = sk + ATT_KV_B;
        #pragma unroll
        for (int i = 0; i < 2; i++) {
            const int idx = tid + i * 256;
            const int row = idx >> 3, c = idx & 7;
            CP_ASYNC16(sk + (uint32_t)(row * KROWB + c * 16), Kp + (size_t)row * QS + c * 8);
            CP_ASYNC16(sv + (uint32_t)(row * KROWB + c * 16), Vp + (size_t)row * QS + c * 8);
        }
    }
    CP_COMMIT();
    {
        const uint32_t sk = sb + ATT_SQ_B + 2 * ATT_KV_B, sv = sk + ATT_KV_B;
        #pragma unroll
        for (int i = 0; i < 2; i++) {
            const int idx = tid + i * 256;
            const int row = idx >> 3, c = idx & 7;
            CP_ASYNC16(sk + (uint32_t)(row * KROWB + c * 16), Kp + (size_t)(64 + row) * QS + c * 8);
            CP_ASYNC16(sv + (uint32_t)(row * KROWB + c * 16), Vp + (size_t)(64 + row) * QS + c * 8);
        }
    }
    CP_COMMIT();

    const int g = lane >> 3, r8 = lane & 7;

    CP_WAIT1();
    __syncthreads();

    uint32_t qa[4][4];
    {
        const uint32_t ao = sQ + (uint32_t)((warp * 16 + (g & 1) * 8 + r8) * KROWB + (g >> 1) * 16);
        #pragma unroll
        for (int kf = 0; kf < 4; kf++)
            LDMATRIX_X4(qa[kf][0], qa[kf][1], qa[kf][2], qa[kf][3], ao + kf * 32);
    }

    float oacc[8][4];
    #pragma unroll
    for (int i = 0; i < 8; i++)
        #pragma unroll
        for (int c = 0; c < 4; c++) oacc[i][c] = 0.0f;
    float mrun0 = -1e30f, mrun1 = -1e30f, lrun0 = 0.0f, lrun1 = 0.0f;

    const uint32_t koff = (uint32_t)(((g >> 1) * 8 + r8) * KROWB + (g & 1) * 16);
    const uint32_t voff = (uint32_t)(((g & 1) * 8 + r8) * KROWB + (g >> 1) * 16);

    int stage = 0;
    for (int kb = 0; kb < NKB; kb++) {
        if (kb == NKB - 1) CP_WAIT0(); else CP_WAIT1();
        __syncthreads();

        const uint32_t sk = sb + ATT_SQ_B + (uint32_t)stage * (2 * ATT_KV_B);
        const uint32_t sv = sk + ATT_KV_B;

        if (kb + 2 < NKB) {
            int ns = stage + 2; if (ns >= 3) ns -= 3;
            const uint32_t nk = sb + ATT_SQ_B + (uint32_t)ns * (2 * ATT_KV_B);
            const uint32_t nv = nk + ATT_KV_B;
            const int rbase = (kb + 2) * 64;
            #pragma unroll
            for (int i = 0; i < 2; i++) {
                const int idx = tid + i * 256;
                const int row = idx >> 3, c = idx & 7;
                CP_ASYNC16(nk + (uint32_t)(row * KROWB + c * 16), Kp + (size_t)(rbase + row) * QS + c * 8);
                CP_ASYNC16(nv + (uint32_t)(row * KROWB + c * 16), Vp + (size_t)(rbase + row) * QS + c * 8);
            }
            CP_COMMIT();
        }

        // ---- S' = (Q*log2e/8) @ K^T  (exp2 domain) ----
        float sf[8][4];
        #pragma unroll
        for (int i = 0; i < 8; i++)
            #pragma unroll
            for (int c = 0; c < 4; c++) sf[i][c] = 0.0f;

        #pragma unroll
        for (int kf = 0; kf < 4; kf++) {
            uint32_t kbv[8][2];
            const uint32_t bo = sk + koff + kf * 32;
            #pragma unroll
            for (int np = 0; np < 4; np++)
                LDMATRIX_X4(kbv[np * 2][0], kbv[np * 2][1], kbv[np * 2 + 1][0], kbv[np * 2 + 1][1],
                            bo + np * (16 * KROWB));
            #pragma unroll
            for (int ni = 0; ni < 8; ni++)
                MMA16816(sf[ni], qa[kf], kbv[ni]);
        }

        // ---- online softmax (exp2 domain) ----
        float mx0 = -1e30f, mx1 = -1e30f;
        #pragma unroll
        for (int ni = 0; ni < 8; ni++) {
            mx0 = fmaxf(mx0, fmaxf(sf[ni][0], sf[ni][1]));
            mx1 = fmaxf(mx1, fmaxf(sf[ni][2], sf[ni][3]));
        }
        mx0 = fmaxf(mx0, __shfl_xor_sync(0xffffffffu, mx0, 1));
        mx0 = fmaxf(mx0, __shfl_xor_sync(0xffffffffu, mx0, 2));
        mx1 = fmaxf(mx1, __shfl_xor_sync(0xffffffffu, mx1, 1));
        mx1 = fmaxf(mx1, __shfl_xor_sync(0xffffffffu, mx1, 2));

        const float mn0 = fmaxf(mrun0, mx0), mn1 = fmaxf(mrun1, mx1);
        const float cr0 = exp2f(mrun0 - mn0), cr1 = exp2f(mrun1 - mn1);
        float s0 = 0.0f, s1 = 0.0f;
        #pragma unroll
        for (int ni = 0; ni < 8; ni++) {
            sf[ni][0] = exp2f(sf[ni][0] - mn0); s0 += sf[ni][0];
            sf[ni][1] = exp2f(sf[ni][1] - mn0); s0 += sf[ni][1];
            sf[ni][2] = exp2f(sf[ni][2] - mn1); s1 += sf[ni][2];
            sf[ni][3] = exp2f(sf[ni][3] - mn1); s1 += sf[ni][3];
        }
        s0 += __shfl_xor_sync(0xffffffffu, s0, 1);
        s0 += __shfl_xor_sync(0xffffffffu, s0, 2);
        s1 += __shfl_xor_sync(0xffffffffu, s1, 1);
        s1 += __shfl_xor_sync(0xffffffffu, s1, 2);
        lrun0 = lrun0 * cr0 + s0;
        lrun1 = lrun1 * cr1 + s1;
        #pragma unroll
        for (int ni = 0; ni < 8; ni++) {
            oacc[ni][0] *= cr0; oacc[ni][1] *= cr0;
            oacc[ni][2] *= cr1; oacc[ni][3] *= cr1;
        }
        mrun0 = mn0; mrun1 = mn1;

        // ---- O += P @ V ----
        #pragma unroll
        for (int kf = 0; kf < 4; kf++) {
            uint32_t pa[4];
            pa[0] = h2pack(sf[2 * kf][0],     sf[2 * kf][1]);
            pa[1] = h2pack(sf[2 * kf][2],     sf[2 * kf][3]);
            pa[2] = h2pack(sf[2 * kf + 1][0], sf[2 * kf + 1][1]);
            pa[3] = h2pack(sf[2 * kf + 1][2], sf[2 * kf + 1][3]);

            uint32_t vb[8][2];
            const uint32_t vo = sv + voff + kf * (16 * KROWB);
            #pragma unroll
            for (int np = 0; np < 4; np++)
                LDMATRIX_X4_TRANS(vb[np * 2][0], vb[np * 2][1], vb[np * 2 + 1][0], vb[np * 2 + 1][1],
                                  vo + np * 32);
            #pragma unroll
            for (int ni = 0; ni < 8; ni++)
                MMA16816(oacc[ni], pa, vb[ni]);
        }

        if (++stage == 3) stage = 0;
    }

    // ---- write ctx ----
    const float i0 = 1.0f / lrun0, i1 = 1.0f / lrun1;
    const int tok = q0 + warp * 16 + (lane >> 2);
    half* p0 = ctx + (size_t)(b * SEQ + tok) * D_MODEL + h * DK + (lane & 3) * 2;
    half* p1 = p0 + 8 * D_MODEL;
    #pragma unroll
    for (int ni = 0; ni < 8; ni++) {
        *(half2*)(p0 + ni * 8) = __floats2half2_rn(oacc[ni][0] * i0, oacc[ni][1] * i0);
        *(half2*)(p1 + ni * 8) = __floats2half2_rn(oacc[ni][2] * i1, oacc[ni][3] * i1);
    }
}

// ------------------- LayerNorm (single-pass stats) --------------------------
template <bool HOUT>
__global__ void __launch_bounds__(256) ln_kernel(
    const float* __restrict__ X, const float* __restrict__ G,
    const float* __restrict__ Bb, float* __restrict__ Y, half* __restrict__ Yh)
{
    __shared__ float redS[8];
    __shared__ float redQ[8];
    __shared__ float stat[2];
    const int row = blockIdx.x;
    const int tid = threadIdx.x;
    const int lane = tid & 31, warp = tid >> 5;

    float4 v = *(const float4*)(X + (size_t)row * D_MODEL + tid * 4);

    float s = v.x + v.y + v.z + v.w;
    float q = v.x * v.x + v.y * v.y + v.z * v.z + v.w * v.w;
    #pragma unroll
    for (int o = 16; o; o >>= 1) {
        s += __shfl_xor_sync(0xffffffffu, s, o);
        q += __shfl_xor_sync(0xffffffffu, q, o);
    }
    if (lane == 0) { redS[warp] = s; redQ[warp] = q; }
    __syncthreads();
    if (tid == 0) {
        float ts = 0.0f, tq = 0.0f;
        #pragma unroll
        for (int i = 0; i < 8; i++) { ts += redS[i]; tq += redQ[i]; }
        const float mu = ts * (1.0f / D_MODEL);
        stat[0] = mu;
        stat[1] = rsqrtf(tq * (1.0f / D_MODEL) - mu * mu + EPS);
    }
    __syncthreads();
    const float mu = stat[0];
    const float rstd = stat[1];

    const int c = tid * 4;
    float4 gg = *(const float4*)(G + c);
    float4 bb = *(const float4*)(Bb + c);
    float4 o;
    o.x = (v.x - mu) * rstd * gg.x + bb.x;
    o.y = (v.y - mu) * rstd * gg.y + bb.y;
    o.z = (v.z - mu) * rstd * gg.z + bb.z;
    o.w = (v.w - mu) * rstd * gg.w + bb.w;
    *(float4*)(Y + (size_t)row * D_MODEL + c) = o;

    if (HOUT) {
        *(half2*)(Yh + (size_t)row * D_MODEL + c)     = __floats2half2_rn(o.x, o.y);
        *(half2*)(Yh + (size_t)row * D_MODEL + c + 2) = __floats2half2_rn(o.z, o.w);
    }
}

// ------------------------------ launch -------------------------------------
extern "C" void kernel_launch(void* const* d_in, const int* in_sizes, int n_in,
                              void* d_out, int out_size)
{
    const float* x     = (const float*)d_in[0];
    const float* wq    = (const float*)d_in[1];
    const float* bq    = (const float*)d_in[2];
    const float* wk    = (const float*)d_in[3];
    const float* bk    = (const float*)d_in[4];
    const float* wv    = (const float*)d_in[5];
    const float* bv    = (const float*)d_in[6];
    const float* wo    = (const float*)d_in[7];
    const float* bo    = (const float*)d_in[8];
    const float* ln1_g = (const float*)d_in[9];
    const float* ln1_b = (const float*)d_in[10];
    const float* w1    = (const float*)d_in[11];
    const float* b1    = (const float*)d_in[12];
    const float* w2    = (const float*)d_in[13];
    const float* b2    = (const float*)d_in[14];
    const float* ln2_g = (const float*)d_in[15];
    const float* ln2_b = (const float*)d_in[16];
    float* out = (float*)d_out;

    half *qkv, *ctx, *xh, *ath, *hh, *wqkvh, *woh, *w1h, *w2h;
    float *y, *attn, *bqkv;
    cudaGetSymbolAddress((void**)&qkv,   g_qkv);
    cudaGetSymbolAddress((void**)&ctx,   g_ctx);
    cudaGetSymbolAddress((void**)&xh,    g_xh);
    cudaGetSymbolAddress((void**)&ath,   g_ath);
    cudaGetSymbolAddress((void**)&hh,    g_hh);
    cudaGetSymbolAddress((void**)&y,     g_y);
    cudaGetSymbolAddress((void**)&attn,  g_attn);
    cudaGetSymbolAddress((void**)&wqkvh, g_wqkv);
    cudaGetSymbolAddress((void**)&woh,   g_wo);
    cudaGetSymbolAddress((void**)&w1h,   g_w1);
    cudaGetSymbolAddress((void**)&w2h,   g_w2);
    cudaGetSymbolAddress((void**)&bqkv,  g_bqkv);

    cudaFuncSetAttribute(gemm_mma<MODE_QKV>,  cudaFuncAttributeMaxDynamicSharedMemorySize, GEMM_SMEM);
    cudaFuncSetAttribute(gemm_mma<MODE_RES>,  cudaFuncAttributeMaxDynamicSharedMemorySize, GEMM_SMEM);
    cudaFuncSetAttribute(gemm_mma<MODE_GELU>, cudaFuncAttributeMaxDynamicSharedMemorySize, GEMM_SMEM);
    cudaFuncSetAttribute(attn_tc,             cudaFuncAttributeMaxDynamicSharedMemorySize, ATT_SMEM);

    // 0) one-shot conversion of x + all weights + bias pack
    cvt_all<<<2048, 256>>>(x, wq, wk, wv, wo, w1, w2, bq, bk, bv,
                           xh, wqkvh, woh, w1h, w2h, bqkv);

    const dim3 blk(256);
    const dim3 gQ(3 * D_MODEL / 128, NTOK / 128);   // (24, 32)
    const dim3 gD(D_MODEL / 128,     NTOK / 128);   // (8, 32)
    const dim3 gF(DFF / 128,         NTOK / 128);   // (32, 32)

    // 1) fused QKV projection -> f16 token-major [NTOK, 3072]; Q in exp2 domain
    gemm_mma<MODE_QKV><<<gQ, blk, GEMM_SMEM>>>(xh, wqkvh, bqkv, nullptr, nullptr, qkv,
                                               NTOK, 3 * D_MODEL, D_MODEL);

    // 2) flash attention -> ctx f16
    attn_tc<<<dim3(SEQ / 128, 2 * NHEAD), blk, ATT_SMEM>>>(qkv, ctx);

    // 3) O projection + residual -> y fp32
    gemm_mma<MODE_RES><<<gD, blk, GEMM_SMEM>>>(ctx, woh, bo, x, y, nullptr,
                                               NTOK, D_MODEL, D_MODEL);

    // 4) LN1 -> attn fp32 + ath f16
    ln_kernel<true><<<NTOK, blk>>>(y, ln1_g, ln1_b, attn, ath);

    // 5) FF1 + GELU -> h f16
    gemm_mma<MODE_GELU><<<gF, blk, GEMM_SMEM>>>(ath, w1h, b1, nullptr, nullptr, hh,
                                                NTOK, DFF, D_MODEL);

    // 6) FF2 + residual -> y fp32
    gemm_mma<MODE_RES><<<gD, blk, GEMM_SMEM>>>(hh, w2h, b2, attn, y, nullptr,
                                               NTOK, D_MODEL, DFF);

    // 7) LN2 -> out
    ln_kernel<false><<<NTOK, blk>>>(y, ln2_g, ln2_b, out, nullptr);
}

// round 17
// speedup vs baseline: 1.0784x; 1.0119x over previous
#include <cuda_runtime.h>
#include <cuda_fp16.h>
#include <math.h>
#include <stdint.h>

// ---------------------------------------------------------------------------
// TransformerBlock B=2,S=2048,D=1024,H=16,Dk=64,DFF=4096
// GEMMs: mma.sync f16 single-term, 8 warps x (32x64) per 128x128 CTA,
// 3-stage cp.async. QKV token-major, exp2-domain softmax, single-pass LN.
// R17: f16 inter-kernel plumbing (y buffer f16, f16 residuals, no attn fp32).
// ---------------------------------------------------------------------------

#define D_MODEL 1024
#define NTOK    4096
#define NHEAD   16
#define DK      64
#define DFF     4096
#define SEQ     2048
#define EPS     1e-5f
#define QS      3072              // qkv token-major row stride (elements)
#define QSCALE  0.180336880111120f  // 0.125 * log2(e)

// ------------------------- scratch (static device mem) ---------------------
__device__ half  g_qkv[NTOK * 3 * D_MODEL];       // [token, q|k|v] token-major
__device__ half  g_ctx[NTOK * D_MODEL];
__device__ half  g_xh[NTOK * D_MODEL];
__device__ half  g_ath[NTOK * D_MODEL];
__device__ half  g_hh[NTOK * DFF];
__device__ half  g_yh[NTOK * D_MODEL];            // f16 pre-LN buffer

__device__ half  g_wqkv[3 * D_MODEL * D_MODEL];   // wq | wk | wv rows
__device__ half  g_wo[D_MODEL * D_MODEL];
__device__ half  g_w1[DFF * D_MODEL];
__device__ half  g_w2[D_MODEL * DFF];
__device__ float g_bqkv[3 * D_MODEL];

// ------------------------------ helpers ------------------------------------
__device__ __forceinline__ uint32_t smem_u32(const void* p) {
    uint32_t a;
    asm("{ .reg .u64 t; cvta.to.shared.u64 t, %1; cvt.u32.u64 %0, t; }" : "=r"(a) : "l"(p));
    return a;
}
#define CP_ASYNC16(dst, src) \
    asm volatile("cp.async.cg.shared.global [%0], [%1], 16;" :: "r"(dst), "l"(src))
#define CP_COMMIT() asm volatile("cp.async.commit_group;")
#define CP_WAIT0()  asm volatile("cp.async.wait_group 0;" ::: "memory")
#define CP_WAIT1()  asm volatile("cp.async.wait_group 1;" ::: "memory")

#define LDMATRIX_X4(r0, r1, r2, r3, a) \
    asm volatile("ldmatrix.sync.aligned.m8n8.x4.shared.b16 {%0,%1,%2,%3}, [%4];" \
                 : "=r"(r0), "=r"(r1), "=r"(r2), "=r"(r3) : "r"(a))
#define LDMATRIX_X4_TRANS(r0, r1, r2, r3, a) \
    asm volatile("ldmatrix.sync.aligned.m8n8.x4.trans.shared.b16 {%0,%1,%2,%3}, [%4];" \
                 : "=r"(r0), "=r"(r1), "=r"(r2), "=r"(r3) : "r"(a))

#define MMA16816(c, a, b) \
    asm volatile("mma.sync.aligned.m16n8k16.row.col.f32.f16.f16.f32 " \
                 "{%0,%1,%2,%3}, {%4,%5,%6,%7}, {%8,%9}, {%0,%1,%2,%3};" \
                 : "+f"((c)[0]), "+f"((c)[1]), "+f"((c)[2]), "+f"((c)[3]) \
                 : "r"((a)[0]), "r"((a)[1]), "r"((a)[2]), "r"((a)[3]), \
                   "r"((b)[0]), "r"((b)[1]))

__device__ __forceinline__ float gelu_f(float x) {
    return 0.5f * x * (1.0f + erff(x * 0.70710678118654752f));
}
__device__ __forceinline__ uint32_t h2pack(float a, float b) {
    half2 h = __floats2half2_rn(a, b);
    return *(uint32_t*)&h;
}

// ------------------------------ MMA GEMM -----------------------------------
// C[M,N] = A_f16[M,K] @ W_f16[N,K]^T  (fp32 accum). BM=BN=128, BK=64, 3-stage.
#define MODE_QKV  1
#define MODE_RES  2   // + f16 residual, f16 output
#define MODE_GELU 3

#define ROWB   144               // 64 f16 = 128B data + 16B pad (conflict-free)
#define TILEB  (128 * ROWB)      // 18432
#define STAGEB (2 * TILEB)       // 36864 (A + B)
#define GEMM_SMEM (3 * STAGEB)   // 110592

template <int MODE>
__global__ void __launch_bounds__(256, 2) gemm_mma(
    const half* __restrict__ A, const half* __restrict__ W,
    const float* __restrict__ bias, const half* __restrict__ resH,
    half* __restrict__ Ch,
    int M, int N, int K)
{
    extern __shared__ __align__(128) char dsm[];
    const uint32_t sbase = smem_u32(dsm);

    const int tid    = threadIdx.x;
    const int lane   = tid & 31;
    const int warp   = tid >> 5;
    const int warp_m = warp & 3;        // 4 along M -> 32 rows each
    const int warp_n = warp >> 2;       // 2 along N -> 64 cols each
    const int brow   = blockIdx.y * 128;
    const int bcol   = blockIdx.x * 128;

    const half* Ap = A + (size_t)brow * K;
    const half* Wp = W + (size_t)bcol * K;

    // ldmatrix lane addresses
    const int g = lane >> 3, r = lane & 7;
    const uint32_t aoff = (uint32_t)((warp_m * 32 + (g & 1) * 8 + r) * ROWB + (g >> 1) * 16);
    const uint32_t boff = (uint32_t)((warp_n * 64 + (g >> 1) * 8 + r) * ROWB + (g & 1) * 16);

    float acc[2][8][4];
    #pragma unroll
    for (int i = 0; i < 2; i++)
        #pragma unroll
        for (int j = 0; j < 8; j++)
            #pragma unroll
            for (int c = 0; c < 4; c++) acc[i][j][c] = 0.0f;

    const int T = K >> 6;   // BK = 64

    // prologue: issue stages 0 and 1 as two commit groups
    #pragma unroll
    for (int s = 0; s < 2; s++) {
        const uint32_t st = sbase + (uint32_t)s * STAGEB;
        const int k0 = s * 64;
        #pragma unroll
        for (int i = 0; i < 4; i++) {
            const int idx = tid + i * 256;
            const int row = idx >> 3, c = idx & 7;
            const uint32_t so = (uint32_t)(row * ROWB + c * 16);
            CP_ASYNC16(st + so,         Ap + (size_t)row * K + k0 + c * 8);
            CP_ASYNC16(st + TILEB + so, Wp + (size_t)row * K + k0 + c * 8);
        }
        CP_COMMIT();
    }

    int stage = 0;
    for (int t = 0; t < T; t++) {
        if (t == T - 1) CP_WAIT0(); else CP_WAIT1();
        __syncthreads();

        const uint32_t cur = sbase + (uint32_t)stage * STAGEB;

        if (t + 2 < T) {
            const int k0 = (t + 2) * 64;
            int ns = stage + 2; if (ns >= 3) ns -= 3;
            const uint32_t nxt = sbase + (uint32_t)ns * STAGEB;
            #pragma unroll
            for (int i = 0; i < 4; i++) {
                const int idx = tid + i * 256;
                const int row = idx >> 3, c = idx & 7;
                const uint32_t so = (uint32_t)(row * ROWB + c * 16);
                CP_ASYNC16(nxt + so,         Ap + (size_t)row * K + k0 + c * 8);
                CP_ASYNC16(nxt + TILEB + so, Wp + (size_t)row * K + k0 + c * 8);
            }
            CP_COMMIT();
        }

        const uint32_t sA = cur + aoff;
        const uint32_t sB = cur + TILEB + boff;

        #pragma unroll
        for (int ks = 0; ks < 4; ks++) {
            const uint32_t ko = ks * 32;   // 16 f16 = 32B
            uint32_t a[2][4], bb[8][2];

            #pragma unroll
            for (int mi = 0; mi < 2; mi++)
                LDMATRIX_X4(a[mi][0], a[mi][1], a[mi][2], a[mi][3],
                            sA + mi * (16 * ROWB) + ko);
            #pragma unroll
            for (int np = 0; np < 4; np++)
                LDMATRIX_X4(bb[np * 2][0], bb[np * 2][1], bb[np * 2 + 1][0], bb[np * 2 + 1][1],
                            sB + np * (16 * ROWB) + ko);
            #pragma unroll
            for (int mi = 0; mi < 2; mi++)
                #pragma unroll
                for (int ni = 0; ni < 8; ni++)
                    MMA16816(acc[mi][ni], a[mi], bb[ni]);
        }

        if (++stage == 3) stage = 0;
    }

    // ------------------------------ epilogue -------------------------------
    const int mbase = brow + warp_m * 32 + (lane >> 2);
    const int nbase = bcol + warp_n * 64 + (lane & 3) * 2;

    #pragma unroll
    for (int mi = 0; mi < 2; mi++) {
        #pragma unroll
        for (int half_ = 0; half_ < 2; half_++) {
            const int m = mbase + mi * 16 + half_ * 8;
            #pragma unroll
            for (int ni = 0; ni < 8; ni++) {
                const int n = nbase + ni * 8;
                float vx = acc[mi][ni][half_ * 2 + 0];
                float vy = acc[mi][ni][half_ * 2 + 1];
                const float2 bb2 = *(const float2*)(bias + n);
                vx += bb2.x; vy += bb2.y;
                if (MODE == MODE_RES) {
                    const half2 rr = *(const half2*)(resH + (size_t)m * N + n);
                    vx += __half2float(rr.x);
                    vy += __half2float(rr.y);
                    *(half2*)(Ch + (size_t)m * N + n) = __floats2half2_rn(vx, vy);
                } else if (MODE == MODE_QKV) {
                    // token-major [NTOK, 3072]; Q cols scaled into exp2 domain
                    const float sc = (n < D_MODEL) ? QSCALE : 1.0f;
                    *(half2*)(Ch + (size_t)m * QS + n) = __floats2half2_rn(vx * sc, vy * sc);
                } else {  // GELU
                    *(half2*)(Ch + (size_t)m * N + n) = __floats2half2_rn(gelu_f(vx), gelu_f(vy));
                }
            }
        }
    }
}

// ---------------- fused conversion kernel (all weights + x + bias) ---------
#define U_X   524288u
#define U_W   131072u
#define B0    (U_X)
#define B1    (B0 + U_W)
#define B2    (B1 + U_W)
#define B3    (B2 + U_W)
#define B4    (B3 + U_W)
#define B5    (B4 + U_X)
#define B6    (B5 + U_X)

__global__ void __launch_bounds__(256) cvt_all(
    const float* __restrict__ x,
    const float* __restrict__ wq, const float* __restrict__ wk,
    const float* __restrict__ wv, const float* __restrict__ wo,
    const float* __restrict__ w1, const float* __restrict__ w2,
    const float* __restrict__ bq, const float* __restrict__ bk,
    const float* __restrict__ bv,
    half* __restrict__ xh, half* __restrict__ wqkvh, half* __restrict__ woh,
    half* __restrict__ w1h, half* __restrict__ w2h, float* __restrict__ bqkv)
{
    const uint32_t gtid = blockIdx.x * blockDim.x + threadIdx.x;
    const uint32_t gstride = gridDim.x * blockDim.x;

    if (gtid < 768) {
        float4 v = (gtid < 256) ? ((const float4*)bq)[gtid]
                 : (gtid < 512) ? ((const float4*)bk)[gtid - 256]
                                : ((const float4*)bv)[gtid - 512];
        ((float4*)bqkv)[gtid] = v;
    }

    for (uint32_t u = gtid; u < B6; u += gstride) {
        const float* src; half* dst; uint32_t off;
        if (u < B0)      { src = x;  dst = xh;                off = u; }
        else if (u < B1) { src = wq; dst = wqkvh;             off = u - B0; }
        else if (u < B2) { src = wk; dst = wqkvh + 1048576;   off = u - B1; }
        else if (u < B3) { src = wv; dst = wqkvh + 2097152;   off = u - B2; }
        else if (u < B4) { src = wo; dst = woh;               off = u - B3; }
        else if (u < B5) { src = w1; dst = w1h;               off = u - B4; }
        else             { src = w2; dst = w2h;               off = u - B5; }

        const float4 v0 = ((const float4*)src)[off * 2 + 0];
        const float4 v1 = ((const float4*)src)[off * 2 + 1];
        uint4 o;
        o.x = h2pack(v0.x, v0.y);
        o.y = h2pack(v0.z, v0.w);
        o.z = h2pack(v1.x, v1.y);
        o.w = h2pack(v1.z, v1.w);
        ((uint4*)dst)[off] = o;
    }
}

// ---------------------- tensor-core flash attention ------------------------
// Q pre-scaled into exp2 domain. qkv token-major [NTOK,3072].
// ctx: [B, S, 1024] f16. 3-stage K/V pipeline, 64-key blocks, 8 warps.
#define KROWB 144
#define ATT_SQ_B  (128 * KROWB)              // 18432
#define ATT_KV_B  (64 * KROWB)               // 9216
#define ATT_SMEM  (ATT_SQ_B + 6 * ATT_KV_B)  // 73728
#define NKB       (SEQ / 64)                 // 32

__global__ void __launch_bounds__(256, 2) attn_tc(
    const half* __restrict__ qkv, half* __restrict__ ctx)
{
    extern __shared__ __align__(128) char sm[];
    const uint32_t sb = smem_u32(sm);
    const uint32_t sQ = sb;

    const int tid  = threadIdx.x;
    const int lane = tid & 31;
    const int warp = tid >> 5;
    const int bh   = blockIdx.y;
    const int q0   = blockIdx.x * 128;
    const int b    = bh >> 4, h = bh & 15;

    const half* Qp = qkv + ((size_t)(b * SEQ + q0)) * QS + h * DK;
    const half* Kp = qkv + ((size_t)(b * SEQ)) * QS + h * DK + D_MODEL;
    const half* Vp = qkv + ((size_t)(b * SEQ)) * QS + h * DK + 2 * D_MODEL;

    #pragma unroll
    for (int i = 0; i < 4; i++) {
        const int idx = tid + i * 256;
        const int row = idx >> 3, c = idx & 7;
        CP_ASYNC16(sQ + (uint32_t)(row * KROWB + c * 16), Qp + (size_t)row * QS + c * 8);
    }
    {
        const uint32_t sk = sb + ATT_SQ_B, sv = sk + ATT_KV_B;
        #pragma unroll
        for (int i = 0; i < 2; i++) {
            const int idx = tid + i * 256;
            const int row = idx >> 3, c = idx & 7;
            CP_ASYNC16(sk + (uint32_t)(row * KROWB + c * 16), Kp + (size_t)row * QS + c * 8);
            CP_ASYNC16(sv + (uint32_t)(row * KROWB + c * 16), Vp + (size_t)row * QS + c * 8);
        }
    }
    CP_COMMIT();
    {
        const uint32_t sk = sb + ATT_SQ_B + 2 * ATT_KV_B, sv = sk + ATT_KV_B;
        #pragma unroll
        for (int i = 0; i < 2; i++) {
            const int idx = tid + i * 256;
            const int row = idx >> 3, c = idx & 7;
            CP_ASYNC16(sk + (uint32_t)(row * KROWB + c * 16), Kp + (size_t)(64 + row) * QS + c * 8);
            CP_ASYNC16(sv + (uint32_t)(row * KROWB + c * 16), Vp + (size_t)(64 + row) * QS + c * 8);
        }
    }
    CP_COMMIT();

    const int g = lane >> 3, r8 = lane & 7;

    CP_WAIT1();
    __syncthreads();

    uint32_t qa[4][4];
    {
        const uint32_t ao = sQ + (uint32_t)((warp * 16 + (g & 1) * 8 + r8) * KROWB + (g >> 1) * 16);
        #pragma unroll
        for (int kf = 0; kf < 4; kf++)
            LDMATRIX_X4(qa[kf][0], qa[kf][1], qa[kf][2], qa[kf][3], ao + kf * 32);
    }

    float oacc[8][4];
    #pragma unroll
    for (int i = 0; i < 8; i++)
        #pragma unroll
        for (int c = 0; c < 4; c++) oacc[i][c] = 0.0f;
    float mrun0 = -1e30f, mrun1 = -1e30f, lrun0 = 0.0f, lrun1 = 0.0f;

    const uint32_t koff = (uint32_t)(((g >> 1) * 8 + r8) * KROWB + (g & 1) * 16);
    const uint32_t voff = (uint32_t)(((g & 1) * 8 + r8) * KROWB + (g >> 1) * 16);

    int stage = 0;
    for (int kb = 0; kb < NKB; kb++) {
        if (kb == NKB - 1) CP_WAIT0(); else CP_WAIT1();
        __syncthreads();

        const uint32_t sk = sb + ATT_SQ_B + (uint32_t)stage * (2 * ATT_KV_B);
        const uint32_t sv = sk + ATT_KV_B;

        if (kb + 2 < NKB) {
            int ns = stage + 2; if (ns >= 3) ns -= 3;
            const uint32_t nk = sb + ATT_SQ_B + (uint32_t)ns * (2 * ATT_KV_B);
            const uint32_t nv = nk + ATT_KV_B;
            const int rbase = (kb + 2) * 64;
            #pragma unroll
            for (int i = 0; i < 2; i++) {
                const int idx = tid + i * 256;
                const int row = idx >> 3, c = idx & 7;
                CP_ASYNC16(nk + (uint32_t)(row * KROWB + c * 16), Kp + (size_t)(rbase + row) * QS + c * 8);
                CP_ASYNC16(nv + (uint32_t)(row * KROWB + c * 16), Vp + (size_t)(rbase + row) * QS + c * 8);
            }
            CP_COMMIT();
        }

        // ---- S' = (Q*log2e/8) @ K^T  (exp2 domain) ----
        float sf[8][4];
        #pragma unroll
        for (int i = 0; i < 8; i++)
            #pragma unroll
            for (int c = 0; c < 4; c++) sf[i][c] = 0.0f;

        #pragma unroll
        for (int kf = 0; kf < 4; kf++) {
            uint32_t kbv[8][2];
            const uint32_t bo = sk + koff + kf * 32;
            #pragma unroll
            for (int np = 0; np < 4; np++)
                LDMATRIX_X4(kbv[np * 2][0], kbv[np * 2][1], kbv[np * 2 + 1][0], kbv[np * 2 + 1][1],
                            bo + np * (16 * KROWB));
            #pragma unroll
            for (int ni = 0; ni < 8; ni++)
                MMA16816(sf[ni], qa[kf], kbv[ni]);
        }

        // ---- online softmax (exp2 domain) ----
        float mx0 = -1e30f, mx1 = -1e30f;
        #pragma unroll
        for (int ni = 0; ni < 8; ni++) {
            mx0 = fmaxf(mx0, fmaxf(sf[ni][0], sf[ni][1]));
            mx1 = fmaxf(mx1, fmaxf(sf[ni][2], sf[ni][3]));
        }
        mx0 = fmaxf(mx0, __shfl_xor_sync(0xffffffffu, mx0, 1));
        mx0 = fmaxf(mx0, __shfl_xor_sync(0xffffffffu, mx0, 2));
        mx1 = fmaxf(mx1, __shfl_xor_sync(0xffffffffu, mx1, 1));
        mx1 = fmaxf(mx1, __shfl_xor_sync(0xffffffffu, mx1, 2));

        const float mn0 = fmaxf(mrun0, mx0), mn1 = fmaxf(mrun1, mx1);
        const float cr0 = exp2f(mrun0 - mn0), cr1 = exp2f(mrun1 - mn1);
        float s0 = 0.0f, s1 = 0.0f;
        #pragma unroll
        for (int ni = 0; ni < 8; ni++) {
            sf[ni][0] = exp2f(sf[ni][0] - mn0); s0 += sf[ni][0];
            sf[ni][1] = exp2f(sf[ni][1] - mn0); s0 += sf[ni][1];
            sf[ni][2] = exp2f(sf[ni][2] - mn1); s1 += sf[ni][2];
            sf[ni][3] = exp2f(sf[ni][3] - mn1); s1 += sf[ni][3];
        }
        s0 += __shfl_xor_sync(0xffffffffu, s0, 1);
        s0 += __shfl_xor_sync(0xffffffffu, s0, 2);
        s1 += __shfl_xor_sync(0xffffffffu, s1, 1);
        s1 += __shfl_xor_sync(0xffffffffu, s1, 2);
        lrun0 = lrun0 * cr0 + s0;
        lrun1 = lrun1 * cr1 + s1;
        #pragma unroll
        for (int ni = 0; ni < 8; ni++) {
            oacc[ni][0] *= cr0; oacc[ni][1] *= cr0;
            oacc[ni][2] *= cr1; oacc[ni][3] *= cr1;
        }
        mrun0 = mn0; mrun1 = mn1;

        // ---- O += P @ V ----
        #pragma unroll
        for (int kf = 0; kf < 4; kf++) {
            uint32_t pa[4];
            pa[0] = h2pack(sf[2 * kf][0],     sf[2 * kf][1]);
            pa[1] = h2pack(sf[2 * kf][2],     sf[2 * kf][3]);
            pa[2] = h2pack(sf[2 * kf + 1][0], sf[2 * kf + 1][1]);
            pa[3] = h2pack(sf[2 * kf + 1][2], sf[2 * kf + 1][3]);

            uint32_t vb[8][2];
            const uint32_t vo = sv + voff + kf * (16 * KROWB);
            #pragma unroll
            for (int np = 0; np < 4; np++)
                LDMATRIX_X4_TRANS(vb[np * 2][0], vb[np * 2][1], vb[np * 2 + 1][0], vb[np * 2 + 1][1],
                                  vo + np * 32);
            #pragma unroll
            for (int ni = 0; ni < 8; ni++)
                MMA16816(oacc[ni], pa, vb[ni]);
        }

        if (++stage == 3) stage = 0;
    }

    // ---- write ctx ----
    const float i0 = 1.0f / lrun0, i1 = 1.0f / lrun1;
    const int tok = q0 + warp * 16 + (lane >> 2);
    half* p0 = ctx + (size_t)(b * SEQ + tok) * D_MODEL + h * DK + (lane & 3) * 2;
    half* p1 = p0 + 8 * D_MODEL;
    #pragma unroll
    for (int ni = 0; ni < 8; ni++) {
        *(half2*)(p0 + ni * 8) = __floats2half2_rn(oacc[ni][0] * i0, oacc[ni][1] * i0);
        *(half2*)(p1 + ni * 8) = __floats2half2_rn(oacc[ni][2] * i1, oacc[ni][3] * i1);
    }
}

// ------------- LayerNorm (f16 input, single-pass stats) ---------------------
// FINAL: write fp32 output. else: write f16 output.
template <bool FINAL>
__global__ void __launch_bounds__(256) ln_kernel(
    const half* __restrict__ X, const float* __restrict__ G,
    const float* __restrict__ Bb, float* __restrict__ Y, half* __restrict__ Yh)
{
    __shared__ float redS[8];
    __shared__ float redQ[8];
    __shared__ float stat[2];
    const int row = blockIdx.x;
    const int tid = threadIdx.x;
    const int lane = tid & 31, warp = tid >> 5;

    const uint2 raw = *(const uint2*)(X + (size_t)row * D_MODEL + tid * 4);
    const half2 h0 = *(const half2*)&raw.x;
    const half2 h1 = *(const half2*)&raw.y;
    float4 v;
    v.x = __half2float(h0.x); v.y = __half2float(h0.y);
    v.z = __half2float(h1.x); v.w = __half2float(h1.y);

    float s = v.x + v.y + v.z + v.w;
    float q = v.x * v.x + v.y * v.y + v.z * v.z + v.w * v.w;
    #pragma unroll
    for (int o = 16; o; o >>= 1) {
        s += __shfl_xor_sync(0xffffffffu, s, o);
        q += __shfl_xor_sync(0xffffffffu, q, o);
    }
    if (lane == 0) { redS[warp] = s; redQ[warp] = q; }
    __syncthreads();
    if (tid == 0) {
        float ts = 0.0f, tq = 0.0f;
        #pragma unroll
        for (int i = 0; i < 8; i++) { ts += redS[i]; tq += redQ[i]; }
        const float mu = ts * (1.0f / D_MODEL);
        stat[0] = mu;
        stat[1] = rsqrtf(tq * (1.0f / D_MODEL) - mu * mu + EPS);
    }
    __syncthreads();
    const float mu = stat[0];
    const float rstd = stat[1];

    const int c = tid * 4;
    float4 gg = *(const float4*)(G + c);
    float4 bb = *(const float4*)(Bb + c);
    float4 o;
    o.x = (v.x - mu) * rstd * gg.x + bb.x;
    o.y = (v.y - mu) * rstd * gg.y + bb.y;
    o.z = (v.z - mu) * rstd * gg.z + bb.z;
    o.w = (v.w - mu) * rstd * gg.w + bb.w;

    if (FINAL) {
        *(float4*)(Y + (size_t)row * D_MODEL + c) = o;
    } else {
        *(half2*)(Yh + (size_t)row * D_MODEL + c)     = __floats2half2_rn(o.x, o.y);
        *(half2*)(Yh + (size_t)row * D_MODEL + c + 2) = __floats2half2_rn(o.z, o.w);
    }
}

// ------------------------------ launch -------------------------------------
extern "C" void kernel_launch(void* const* d_in, const int* in_sizes, int n_in,
                              void* d_out, int out_size)
{
    const float* x     = (const float*)d_in[0];
    const float* wq    = (const float*)d_in[1];
    const float* bq    = (const float*)d_in[2];
    const float* wk    = (const float*)d_in[3];
    const float* bk    = (const float*)d_in[4];
    const float* wv    = (const float*)d_in[5];
    const float* bv    = (const float*)d_in[6];
    const float* wo    = (const float*)d_in[7];
    const float* bo    = (const float*)d_in[8];
    const float* ln1_g = (const float*)d_in[9];
    const float* ln1_b = (const float*)d_in[10];
    const float* w1    = (const float*)d_in[11];
    const float* b1    = (const float*)d_in[12];
    const float* w2    = (const float*)d_in[13];
    const float* b2    = (const float*)d_in[14];
    const float* ln2_g = (const float*)d_in[15];
    const float* ln2_b = (const float*)d_in[16];
    float* out = (float*)d_out;

    half *qkv, *ctx, *xh, *ath, *hh, *yh, *wqkvh, *woh, *w1h, *w2h;
    float *bqkv;
    cudaGetSymbolAddress((void**)&qkv,   g_qkv);
    cudaGetSymbolAddress((void**)&ctx,   g_ctx);
    cudaGetSymbolAddress((void**)&xh,    g_xh);
    cudaGetSymbolAddress((void**)&ath,   g_ath);
    cudaGetSymbolAddress((void**)&hh,    g_hh);
    cudaGetSymbolAddress((void**)&yh,    g_yh);
    cudaGetSymbolAddress((void**)&wqkvh, g_wqkv);
    cudaGetSymbolAddress((void**)&woh,   g_wo);
    cudaGetSymbolAddress((void**)&w1h,   g_w1);
    cudaGetSymbolAddress((void**)&w2h,   g_w2);
    cudaGetSymbolAddress((void**)&bqkv,  g_bqkv);

    cudaFuncSetAttribute(gemm_mma<MODE_QKV>,  cudaFuncAttributeMaxDynamicSharedMemorySize, GEMM_SMEM);
    cudaFuncSetAttribute(gemm_mma<MODE_RES>,  cudaFuncAttributeMaxDynamicSharedMemorySize, GEMM_SMEM);
    cudaFuncSetAttribute(gemm_mma<MODE_GELU>, cudaFuncAttributeMaxDynamicSharedMemorySize, GEMM_SMEM);
    cudaFuncSetAttribute(attn_tc,             cudaFuncAttributeMaxDynamicSharedMemorySize, ATT_SMEM);

    // 0) one-shot conversion of x + all weights + bias pack
    cvt_all<<<2048, 256>>>(x, wq, wk, wv, wo, w1, w2, bq, bk, bv,
                           xh, wqkvh, woh, w1h, w2h, bqkv);

    const dim3 blk(256);
    const dim3 gQ(3 * D_MODEL / 128, NTOK / 128);   // (24, 32)
    const dim3 gD(D_MODEL / 128,     NTOK / 128);   // (8, 32)
    const dim3 gF(DFF / 128,         NTOK / 128);   // (32, 32)

    // 1) fused QKV projection -> f16 token-major [NTOK, 3072]; Q in exp2 domain
    gemm_mma<MODE_QKV><<<gQ, blk, GEMM_SMEM>>>(xh, wqkvh, bqkv, nullptr, qkv,
                                               NTOK, 3 * D_MODEL, D_MODEL);

    // 2) flash attention -> ctx f16
    attn_tc<<<dim3(SEQ / 128, 2 * NHEAD), blk, ATT_SMEM>>>(qkv, ctx);

    // 3) O projection + residual(xh) -> yh f16
    gemm_mma<MODE_RES><<<gD, blk, GEMM_SMEM>>>(ctx, woh, bo, xh, yh,
                                               NTOK, D_MODEL, D_MODEL);

    // 4) LN1 -> ath f16
    ln_kernel<false><<<NTOK, blk>>>(yh, ln1_g, ln1_b, nullptr, ath);

    // 5) FF1 + GELU -> hh f16
    gemm_mma<MODE_GELU><<<gF, blk, GEMM_SMEM>>>(ath, w1h, b1, nullptr, hh,
                                                NTOK, DFF, D_MODEL);

    // 6) FF2 + residual(ath) -> yh f16
    gemm_mma<MODE_RES><<<gD, blk, GEMM_SMEM>>>(hh, w2h, b2, ath, yh,
                                               NTOK, D_MODEL, DFF);

    // 7) LN2 -> out fp32
    ln_kernel<true><<<NTOK, blk>>>(yh, ln2_g, ln2_b, out, nullptr);
}